// round 6
// baseline (speedup 1.0000x reference)
#include <cuda_runtime.h>
#include <math.h>
#include <stdint.h>

#define NB 8
#define NE 1024
#define ND 512
#define NQKV 512
#define NH 8
#define NHD 64
#define NBH (NB*NH)         // 64
#define M_ROWS (NB*NE)      // 8192
#define SLAB (NE*NHD)       // 65536
#define LN_EPS 1e-5f
#define ATTN_SCALE 0.044194173824159216f           // 1/sqrt(512)
#define SC2 (ATTN_SCALE * 1.4426950408889634f)     // scale * log2(e)

// ---------------- scratch (device globals; no runtime allocation) -------------
__device__ float g_q[NBH*SLAB];        // (B,H,E,HD), tf32-rounded after LN
__device__ float g_k[NBH*SLAB];
__device__ float g_v[NBH*SLAB];
__device__ float g_ctx[M_ROWS*NQKV];   // (B,E,H,HD), tf32-rounded
// per-CTA LN partial sums: [t][by][bx][half] -> (sum, sumsq); deterministic
__device__ float2 g_part[3*64*4*2];

// ---------------- helpers ------------------------------------------------------
__device__ __forceinline__ float tf32r(float x) {
    uint32_t u;
    asm("cvt.rna.tf32.f32 %0, %1;" : "=r"(u) : "f"(x));
    return __uint_as_float(u);
}
__device__ __forceinline__ float exp2a(float x) {
    float y;
    asm("ex2.approx.ftz.f32 %0, %1;" : "=f"(y) : "f"(x));
    return y;
}
__device__ __forceinline__ void mma8(float c[4], const float a[4], const float b[2]) {
    asm volatile(
        "mma.sync.aligned.m16n8k8.row.col.f32.tf32.tf32.f32 "
        "{%0,%1,%2,%3}, {%4,%5,%6,%7}, {%8,%9}, {%0,%1,%2,%3};\n"
        : "+f"(c[0]), "+f"(c[1]), "+f"(c[2]), "+f"(c[3])
        : "r"(__float_as_uint(a[0])), "r"(__float_as_uint(a[1])),
          "r"(__float_as_uint(a[2])), "r"(__float_as_uint(a[3])),
          "r"(__float_as_uint(b[0])), "r"(__float_as_uint(b[1])));
}
__device__ __forceinline__ void cp_async16(void* smem, const void* gmem) {
    uint32_t s = (uint32_t)__cvta_generic_to_shared(smem);
    asm volatile("cp.async.cg.shared.global [%0], [%1], 16;\n" :: "r"(s), "l"(gmem));
}
#define CP_COMMIT() asm volatile("cp.async.commit_group;\n" ::: "memory")
#define CP_WAIT0()  asm volatile("cp.async.wait_group 0;\n" ::: "memory")
#define CP_WAIT1()  asm volatile("cp.async.wait_group 1;\n" ::: "memory")

// =============================================================================
// tf32 GEMM core: 128x128 block, k-step 32, 3-stage cp.async pipeline,
// 256 threads = 8 warps (2x4), warp tile 64x32, m16n8k8 mma.
//   As: m-major [128][36], Bs: k-major [32][136]  (frag-conflict-free)
// =============================================================================
#define GAP 36
#define GBP 136
#define STG_F (128*GAP + 32*GBP)            // floats per stage
#define GEMM_SMEM (3*STG_F*4)               // 107.5 KB

__device__ __forceinline__ void g_load(
    float* As, float* Bs,
    const float* __restrict__ A, const float* __restrict__ B,
    int by, int bx, int kk, int lda, int ldb, int tid)
{
    #pragma unroll
    for (int l = 0; l < 4; ++l) {
        int idx = l*256 + tid;
        int row = idx >> 3, k4 = (idx & 7) << 2;
        cp_async16(As + row*GAP + k4, A + (size_t)(by*128 + row)*lda + kk + k4);
    }
    #pragma unroll
    for (int l = 0; l < 4; ++l) {
        int idx = l*256 + tid;
        int kr = idx >> 5, n4 = (idx & 31) << 2;
        cp_async16(Bs + kr*GBP + n4, B + (size_t)(kk + kr)*ldb + bx*128 + n4);
    }
    CP_COMMIT();
}

__device__ __forceinline__ void g_compute(
    const float* As, const float* Bs,
    int wr, int wc, int qr, int qc, float c[4][4][4])
{
    #pragma unroll
    for (int kb = 0; kb < 32; kb += 8) {
        float a[4][4], b[4][2];
        #pragma unroll
        for (int mt = 0; mt < 4; ++mt) {
            const float* ap = As + (wr*64 + mt*16 + qr)*GAP + kb + qc;
            a[mt][0] = ap[0];
            a[mt][1] = ap[8*GAP];
            a[mt][2] = ap[4];
            a[mt][3] = ap[8*GAP + 4];
        }
        #pragma unroll
        for (int nt = 0; nt < 4; ++nt) {
            const float* bp = Bs + (kb + qc)*GBP + wc*32 + nt*8 + qr;
            b[nt][0] = bp[0];
            b[nt][1] = bp[4*GBP];
            #pragma unroll
            for (int mt = 0; mt < 4; ++mt)
                mma8(c[mt][nt], a[mt], b[nt]);
        }
    }
}

// 3-stage mainloop shared by both GEMM kernels
__device__ __forceinline__ void g_mainloop(
    float* dsm, const float* __restrict__ A, const float* __restrict__ B,
    int by, int bx, int ktot, int lda, int ldb, int tid,
    int wr, int wc, int qr, int qc, float c[4][4][4])
{
    float* As[3] = { dsm, dsm + STG_F, dsm + 2*STG_F };
    float* Bs[3] = { dsm + 128*GAP, dsm + STG_F + 128*GAP, dsm + 2*STG_F + 128*GAP };

    const int nit = ktot / 32;
    g_load(As[0], Bs[0], A, B, by, bx, 0,  lda, ldb, tid);
    g_load(As[1], Bs[1], A, B, by, bx, 32, lda, ldb, tid);

    int st = 0, ld = 2;
    for (int it = 0; it < nit; ++it) {
        if (it == nit - 1) { CP_WAIT0(); } else { CP_WAIT1(); }
        __syncthreads();   // stage 'it' published; stage (it+2)%3 reads retired
        if (it + 2 < nit) {
            g_load(As[ld], Bs[ld], A, B, by, bx, (it+2)*32, lda, ldb, tid);
            ld = (ld == 2) ? 0 : ld + 1;
        }
        g_compute(As[st], Bs[st], wr, wc, qr, qc, c);
        st = (st == 2) ? 0 : st + 1;
    }
}

// =============================================================================
// Kernel 1: QKV projection (tf32 mma), scatter to (B,H,E,HD),
// fused per-CTA LN partial sums (deterministic, no atomics).
// =============================================================================
__global__ __launch_bounds__(256, 2) void gemm_qkv_kernel(
    const float* __restrict__ X,
    const float* __restrict__ Wq, const float* __restrict__ bq,
    const float* __restrict__ Wk, const float* __restrict__ bk,
    const float* __restrict__ Wv, const float* __restrict__ bv)
{
    extern __shared__ float dsm[];

    const int t = blockIdx.z;
    const float* __restrict__ W    = (t==0) ? Wq : ((t==1) ? Wk : Wv);
    const float* __restrict__ bias = (t==0) ? bq : ((t==1) ? bk : bv);
    float* __restrict__ Y          = (t==0) ? g_q : ((t==1) ? g_k : g_v);

    const int bx = blockIdx.x, by = blockIdx.y;
    const int tid = threadIdx.x;
    const int w = tid >> 5, lane = tid & 31;
    const int wr = w >> 2, wc = w & 3;
    const int qr = lane >> 2, qc = lane & 3;

    float c[4][4][4];
    #pragma unroll
    for (int i = 0; i < 4; ++i)
        #pragma unroll
        for (int j = 0; j < 4; ++j)
            #pragma unroll
            for (int r = 0; r < 4; ++r) c[i][j][r] = 0.f;

    g_mainloop(dsm, X, W, by, bx, ND, ND, NQKV, tid, wr, wc, qr, qc, c);

    // epilogue: bias + scatter + LN partial sums
    float s = 0.f, s2 = 0.f;
    #pragma unroll
    for (int mt = 0; mt < 4; ++mt) {
        #pragma unroll
        for (int nt = 0; nt < 4; ++nt) {
            int gr = by*128 + wr*64 + mt*16 + qr;
            int gc = bx*128 + wc*32 + nt*8 + 2*qc;
            int h  = gc >> 6, hd = gc & 63;
            float bx0 = bias[gc], bx1 = bias[gc+1];
            float y0 = c[mt][nt][0] + bx0, y1 = c[mt][nt][1] + bx1;
            float y2 = c[mt][nt][2] + bx0, y3 = c[mt][nt][3] + bx1;
            s  += y0 + y1 + y2 + y3;
            s2 += y0*y0 + y1*y1 + y2*y2 + y3*y3;
            {
                int bi = gr >> 10, e = gr & 1023;
                float2 v = { y0, y1 };
                *(float2*)(Y + ((size_t)(bi*NH + h)*NE + e)*NHD + hd) = v;
            }
            {
                int gr2 = gr + 8;
                int bi = gr2 >> 10, e = gr2 & 1023;
                float2 v = { y2, y3 };
                *(float2*)(Y + ((size_t)(bi*NH + h)*NE + e)*NHD + hd) = v;
            }
        }
    }
    // warp reduce (all lanes of a warp share the same slab-half wc>>1)
    #pragma unroll
    for (int o = 16; o > 0; o >>= 1) {
        s  += __shfl_xor_sync(0xffffffffu, s,  o);
        s2 += __shfl_xor_sync(0xffffffffu, s2, o);
    }
    __shared__ float2 ws[8];
    if (lane == 0) ws[w] = make_float2(s, s2);
    __syncthreads();
    if (tid < 2) {
        const int half = tid;
        // warps with wc>>1 == half, fixed order -> deterministic
        float2 a0 = ws[2*half], a1 = ws[2*half+1];
        float2 a2 = ws[2*half+4], a3 = ws[2*half+5];
        float2 r = { ((a0.x + a1.x) + (a2.x + a3.x)),
                     ((a0.y + a1.y) + (a2.y + a3.y)) };
        g_part[((t*64 + by)*4 + bx)*2 + half] = r;
    }
}

// =============================================================================
// Kernel 2: LN normalize pass (stats precomputed in g_part) + affine + ReLU,
// in place, output tf32-rounded.
// =============================================================================
__global__ __launch_bounds__(1024) void ln_kernel(
    const float* __restrict__ lw0, const float* __restrict__ lb0,
    const float* __restrict__ lw1, const float* __restrict__ lb1,
    const float* __restrict__ lw2, const float* __restrict__ lb2)
{
    const int t  = blockIdx.y;
    const int bh = blockIdx.x;
    float* __restrict__ Y        = (t==0) ? g_q : ((t==1) ? g_k : g_v);
    const float* __restrict__ lw = (t==0) ? lw0 : ((t==1) ? lw1 : lw2);
    const float* __restrict__ lb = (t==0) ? lb0 : ((t==1) ? lb1 : lb2);
    float* base = Y + (size_t)bh * SLAB;

    const int tid = threadIdx.x;
    __shared__ float bc[2];
    if (tid == 0) {
        const int b = bh >> 3, h = bh & 7;
        float s = 0.f, s2 = 0.f;
        #pragma unroll
        for (int i = 0; i < 8; ++i) {
            float2 p = g_part[((t*64 + (b*8 + i))*4 + (h >> 1))*2 + (h & 1)];
            s += p.x; s2 += p.y;
        }
        float mean = s * (1.f / SLAB);
        float var  = s2 * (1.f / SLAB) - mean*mean;
        bc[0] = mean;
        bc[1] = rsqrtf(var + LN_EPS);
    }
    __syncthreads();
    const float mean = bc[0], rstd = bc[1];

    for (int i = tid*4; i < SLAB; i += 1024*4) {
        float4 v = *(const float4*)(base + i);
        float4 g = *(const float4*)(lw + i);
        float4 b = *(const float4*)(lb + i);
        v.x = tf32r(fmaxf(0.f, (v.x - mean)*rstd*g.x + b.x));
        v.y = tf32r(fmaxf(0.f, (v.y - mean)*rstd*g.y + b.y));
        v.z = tf32r(fmaxf(0.f, (v.z - mean)*rstd*g.z + b.z));
        v.w = tf32r(fmaxf(0.f, (v.w - mean)*rstd*g.w + b.w));
        *(float4*)(base + i) = v;
    }
}

// =============================================================================
// Kernel 3: flash attention (tf32 mma). grid=(8,64), 256 thr = 8 warps.
// Q fragments in registers; K/V double-buffered via cp.async (2-stage).
//   Kb[2]: [128][68], Vb[2]: [128][72], Ss: [128][132]  (206 KB)
// =============================================================================
#define KP 68
#define VP 72
#define SP 132
#define ATTN_SMEM ((2*128*KP + 2*128*VP + 128*SP)*4)

__device__ __forceinline__ void attn_load_kv(
    float* Kb, float* Vb, const float* __restrict__ kgt,
    const float* __restrict__ vgt, int tid)
{
    #pragma unroll
    for (int l = 0; l < 8; ++l) {
        int idx = l*256 + tid;
        int row = idx >> 4, c4 = (idx & 15) << 2;
        cp_async16(Kb + row*KP + c4, kgt + row*NHD + c4);
        cp_async16(Vb + row*VP + c4, vgt + row*NHD + c4);
    }
    CP_COMMIT();
}

__global__ __launch_bounds__(256, 1) void attn_kernel()
{
    extern __shared__ float sm[];
    float* Kb0 = sm;
    float* Kb1 = Kb0 + 128*KP;
    float* Vb0 = Kb1 + 128*KP;
    float* Vb1 = Vb0 + 128*VP;
    float* Ss  = Vb1 + 128*VP;

    const int bh = blockIdx.y;
    const int qb = blockIdx.x;
    const int tid = threadIdx.x;
    const int w = tid >> 5, lane = tid & 31;
    const int qr = lane >> 2, qc = lane & 3;
    const int r0 = w*16 + qr;

    const float* __restrict__ qg = g_q + (size_t)bh*SLAB + (size_t)qb*128*NHD;
    const float* __restrict__ kg = g_k + (size_t)bh*SLAB;
    const float* __restrict__ vg = g_v + (size_t)bh*SLAB;

    attn_load_kv(Kb0, Vb0, kg, vg, tid);

    #pragma unroll
    for (int l = 0; l < 8; ++l) {
        int idx = l*256 + tid;
        int row = idx >> 4, c4 = (idx & 15) << 2;
        *(float4*)(Ss + row*SP + c4) = *(const float4*)(qg + row*NHD + c4);
    }
    __syncthreads();
    float qf[8][4];
    #pragma unroll
    for (int kbi = 0; kbi < 8; ++kbi) {
        const float* ap = Ss + r0*SP + kbi*8 + qc;
        qf[kbi][0] = ap[0];
        qf[kbi][1] = ap[8*SP];
        qf[kbi][2] = ap[4];
        qf[kbi][3] = ap[8*SP + 4];
    }

    float o[8][4];
    #pragma unroll
    for (int nt = 0; nt < 8; ++nt)
        #pragma unroll
        for (int r = 0; r < 4; ++r) o[nt][r] = 0.f;
    float m0 = -INFINITY, m1 = -INFINITY, l0 = 0.f, l1 = 0.f;

    for (int kt = 0; kt < NE/128; ++kt) {
        const int buf = kt & 1;
        float* Kc = buf ? Kb1 : Kb0;
        float* Vc = buf ? Vb1 : Vb0;

        CP_WAIT0();
        __syncthreads();   // publish tile kt; retires PV reads of kt-1

        if (kt + 1 < NE/128) {
            attn_load_kv(buf ? Kb0 : Kb1, buf ? Vb0 : Vb1,
                         kg + (size_t)(kt+1)*128*NHD,
                         vg + (size_t)(kt+1)*128*NHD, tid);
        }

        // ---- S = Q @ K^T
        float s[16][4];
        #pragma unroll
        for (int nt = 0; nt < 16; ++nt)
            #pragma unroll
            for (int r = 0; r < 4; ++r) s[nt][r] = 0.f;

        #pragma unroll
        for (int kbi = 0; kbi < 8; ++kbi) {
            #pragma unroll
            for (int nt = 0; nt < 16; ++nt) {
                const float* bp = Kc + (nt*8 + qr)*KP + kbi*8 + qc;
                float b[2] = { bp[0], bp[4] };
                mma8(s[nt], qf[kbi], b);
            }
        }

        // ---- online softmax
        float mx0 = s[0][0], mx1 = s[0][2];
        #pragma unroll
        for (int nt = 0; nt < 16; ++nt) {
            mx0 = fmaxf(mx0, fmaxf(s[nt][0], s[nt][1]));
            mx1 = fmaxf(mx1, fmaxf(s[nt][2], s[nt][3]));
        }
        mx0 = fmaxf(mx0, __shfl_xor_sync(0xffffffffu, mx0, 1));
        mx0 = fmaxf(mx0, __shfl_xor_sync(0xffffffffu, mx0, 2));
        mx1 = fmaxf(mx1, __shfl_xor_sync(0xffffffffu, mx1, 1));
        mx1 = fmaxf(mx1, __shfl_xor_sync(0xffffffffu, mx1, 2));
        float mn0 = fmaxf(m0, mx0), mn1 = fmaxf(m1, mx1);
        float al0 = exp2a((m0 - mn0)*SC2);
        float al1 = exp2a((m1 - mn1)*SC2);
        m0 = mn0; m1 = mn1;
        l0 *= al0; l1 *= al1;
        #pragma unroll
        for (int nt = 0; nt < 8; ++nt) {
            o[nt][0] *= al0; o[nt][1] *= al0;
            o[nt][2] *= al1; o[nt][3] *= al1;
        }
        const float base0 = mn0*SC2, base1 = mn1*SC2;
        #pragma unroll
        for (int nt = 0; nt < 16; ++nt) {
            float p0 = exp2a(fmaf(s[nt][0], SC2, -base0));
            float p1 = exp2a(fmaf(s[nt][1], SC2, -base0));
            float p2 = exp2a(fmaf(s[nt][2], SC2, -base1));
            float p3 = exp2a(fmaf(s[nt][3], SC2, -base1));
            l0 += p0 + p1;
            l1 += p2 + p3;
            int col = nt*8 + 2*qc;
            float2 v0 = { tf32r(p0), tf32r(p1) };
            float2 v1 = { tf32r(p2), tf32r(p3) };
            *(float2*)(Ss + r0*SP + col)       = v0;
            *(float2*)(Ss + (r0 + 8)*SP + col) = v1;
        }
        __syncthreads();

        // ---- O += P @ V
        #pragma unroll
        for (int kb = 0; kb < 128; kb += 8) {
            float a[4];
            const float* ap = Ss + r0*SP + kb + qc;
            a[0] = ap[0]; a[1] = ap[8*SP]; a[2] = ap[4]; a[3] = ap[8*SP + 4];
            #pragma unroll
            for (int nt = 0; nt < 8; ++nt) {
                const float* bp = Vc + (kb + qc)*VP + nt*8 + qr;
                float b[2] = { bp[0], bp[4*VP] };
                mma8(o[nt], a, b);
            }
        }
    }

    l0 += __shfl_xor_sync(0xffffffffu, l0, 1);
    l0 += __shfl_xor_sync(0xffffffffu, l0, 2);
    l1 += __shfl_xor_sync(0xffffffffu, l1, 1);
    l1 += __shfl_xor_sync(0xffffffffu, l1, 2);
    const float inv0 = 1.f / l0, inv1 = 1.f / l1;

    const int bi = bh >> 3;
    const int h  = bh & 7;
    #pragma unroll
    for (int nt = 0; nt < 8; ++nt) {
        int hd = nt*8 + 2*qc;
        {
            int e = qb*128 + r0;
            float2 v = { tf32r(o[nt][0]*inv0), tf32r(o[nt][1]*inv0) };
            *(float2*)(g_ctx + ((size_t)(bi*NE + e)*NH + h)*NHD + hd) = v;
        }
        {
            int e = qb*128 + r0 + 8;
            float2 v = { tf32r(o[nt][2]*inv1), tf32r(o[nt][3]*inv1) };
            *(float2*)(g_ctx + ((size_t)(bi*NE + e)*NH + h)*NHD + hd) = v;
        }
    }
}

// =============================================================================
// Kernel 4: output projection (tf32 mma) out = relu(ctx @ Wo + bo)
// =============================================================================
__global__ __launch_bounds__(256, 2) void gemm_out_kernel(
    const float* __restrict__ Wo, const float* __restrict__ bo,
    float* __restrict__ out)
{
    extern __shared__ float dsm[];

    const int bx = blockIdx.x, by = blockIdx.y;
    const int tid = threadIdx.x;
    const int w = tid >> 5, lane = tid & 31;
    const int wr = w >> 2, wc = w & 3;
    const int qr = lane >> 2, qc = lane & 3;

    float c[4][4][4];
    #pragma unroll
    for (int i = 0; i < 4; ++i)
        #pragma unroll
        for (int j = 0; j < 4; ++j)
            #pragma unroll
            for (int r = 0; r < 4; ++r) c[i][j][r] = 0.f;

    g_mainloop(dsm, g_ctx, Wo, by, bx, NQKV, NQKV, ND, tid, wr, wc, qr, qc, c);

    #pragma unroll
    for (int mt = 0; mt < 4; ++mt) {
        #pragma unroll
        for (int nt = 0; nt < 4; ++nt) {
            int gr = by*128 + wr*64 + mt*16 + qr;
            int gc = bx*128 + wc*32 + nt*8 + 2*qc;
            float bx0 = bo[gc], bx1 = bo[gc+1];
            float2 v0 = { fmaxf(0.f, c[mt][nt][0] + bx0),
                          fmaxf(0.f, c[mt][nt][1] + bx1) };
            float2 v1 = { fmaxf(0.f, c[mt][nt][2] + bx0),
                          fmaxf(0.f, c[mt][nt][3] + bx1) };
            *(float2*)(out + (size_t)gr*ND + gc)     = v0;
            *(float2*)(out + (size_t)(gr+8)*ND + gc) = v1;
        }
    }
}

// =============================================================================
extern "C" void kernel_launch(void* const* d_in, const int* in_sizes, int n_in,
                              void* d_out, int out_size)
{
    const float* features = (const float*)d_in[0];
    const float* Wq   = (const float*)d_in[1];
    const float* bq   = (const float*)d_in[2];
    const float* lnqw = (const float*)d_in[3];
    const float* lnqb = (const float*)d_in[4];
    const float* Wk   = (const float*)d_in[5];
    const float* bk   = (const float*)d_in[6];
    const float* lnkw = (const float*)d_in[7];
    const float* lnkb = (const float*)d_in[8];
    const float* Wv   = (const float*)d_in[9];
    const float* bv   = (const float*)d_in[10];
    const float* lnvw = (const float*)d_in[11];
    const float* lnvb = (const float*)d_in[12];
    const float* Wo   = (const float*)d_in[13];
    const float* bo   = (const float*)d_in[14];
    float* out = (float*)d_out;

    cudaFuncSetAttribute(attn_kernel,
                         cudaFuncAttributeMaxDynamicSharedMemorySize, ATTN_SMEM);
    cudaFuncSetAttribute(gemm_qkv_kernel,
                         cudaFuncAttributeMaxDynamicSharedMemorySize, GEMM_SMEM);
    cudaFuncSetAttribute(gemm_out_kernel,
                         cudaFuncAttributeMaxDynamicSharedMemorySize, GEMM_SMEM);

    gemm_qkv_kernel<<<dim3(NQKV/128, M_ROWS/128, 3), 256, GEMM_SMEM>>>(
        features, Wq, bq, Wk, bk, Wv, bv);
    ln_kernel<<<dim3(NBH, 3), 1024>>>(lnqw, lnqb, lnkw, lnkb, lnvw, lnvb);
    attn_kernel<<<dim3(NE/128, NBH), 256, ATTN_SMEM>>>();
    gemm_out_kernel<<<dim3(ND/128, M_ROWS/128), 256, GEMM_SMEM>>>(Wo, bo, out);
}

// round 7
// speedup vs baseline: 1.1102x; 1.1102x over previous
#include <cuda_runtime.h>
#include <math.h>
#include <stdint.h>

#define NB 8
#define NE 1024
#define ND 512
#define NQKV 512
#define NH 8
#define NHD 64
#define NBH (NB*NH)         // 64
#define M_ROWS (NB*NE)      // 8192
#define SLAB (NE*NHD)       // 65536
#define LN_EPS 1e-5f
#define ATTN_SCALE 0.044194173824159216f           // 1/sqrt(512)
#define SC2 (ATTN_SCALE * 1.4426950408889634f)     // scale * log2(e)

// ---------------- scratch (device globals; no runtime allocation) -------------
__device__ float g_q[NBH*SLAB];        // (B,H,E,HD), tf32-rounded after LN
__device__ float g_k[NBH*SLAB];
__device__ float g_v[NBH*SLAB];
__device__ float g_ctx[M_ROWS*NQKV];   // (B,E,H,HD), tf32-rounded
// per-CTA LN partial sums: [t][by][bx][half] -> (sum, sumsq); deterministic
__device__ float2 g_part[3*64*4*2];

// ---------------- helpers ------------------------------------------------------
__device__ __forceinline__ float tf32r(float x) {
    uint32_t u;
    asm("cvt.rna.tf32.f32 %0, %1;" : "=r"(u) : "f"(x));
    return __uint_as_float(u);
}
__device__ __forceinline__ float exp2a(float x) {
    float y;
    asm("ex2.approx.ftz.f32 %0, %1;" : "=f"(y) : "f"(x));
    return y;
}
__device__ __forceinline__ void mma8(float c[4], const float a[4], const float b[2]) {
    asm volatile(
        "mma.sync.aligned.m16n8k8.row.col.f32.tf32.tf32.f32 "
        "{%0,%1,%2,%3}, {%4,%5,%6,%7}, {%8,%9}, {%0,%1,%2,%3};\n"
        : "+f"(c[0]), "+f"(c[1]), "+f"(c[2]), "+f"(c[3])
        : "r"(__float_as_uint(a[0])), "r"(__float_as_uint(a[1])),
          "r"(__float_as_uint(a[2])), "r"(__float_as_uint(a[3])),
          "r"(__float_as_uint(b[0])), "r"(__float_as_uint(b[1])));
}
__device__ __forceinline__ void cp_async16(void* smem, const void* gmem) {
    uint32_t s = (uint32_t)__cvta_generic_to_shared(smem);
    asm volatile("cp.async.cg.shared.global [%0], [%1], 16;\n" :: "r"(s), "l"(gmem));
}
#define CP_COMMIT() asm volatile("cp.async.commit_group;\n" ::: "memory")
#define CP_WAIT0()  asm volatile("cp.async.wait_group 0;\n" ::: "memory")

// =============================================================================
// tf32 GEMM core: 128x128 block, k-step 32, 2-stage cp.async (round-5 proven),
// 256 threads = 8 warps (2x4), warp tile 64x32, m16n8k8 mma.
//   As: m-major [128][36], Bs: k-major [32][136]  (frag-conflict-free)
// =============================================================================
#define GAP 36
#define GBP 136
#define GEMM_SMEM ((2*128*GAP + 2*32*GBP)*4)

__device__ __forceinline__ void g_load(
    float* As, float* Bs,
    const float* __restrict__ A, const float* __restrict__ B,
    int by, int bx, int kk, int lda, int ldb, int tid)
{
    #pragma unroll
    for (int l = 0; l < 4; ++l) {
        int idx = l*256 + tid;
        int row = idx >> 3, k4 = (idx & 7) << 2;
        cp_async16(As + row*GAP + k4, A + (size_t)(by*128 + row)*lda + kk + k4);
    }
    #pragma unroll
    for (int l = 0; l < 4; ++l) {
        int idx = l*256 + tid;
        int kr = idx >> 5, n4 = (idx & 31) << 2;
        cp_async16(Bs + kr*GBP + n4, B + (size_t)(kk + kr)*ldb + bx*128 + n4);
    }
    CP_COMMIT();
}

__device__ __forceinline__ void g_compute(
    const float* As, const float* Bs,
    int wr, int wc, int qr, int qc, float c[4][4][4])
{
    #pragma unroll
    for (int kb = 0; kb < 32; kb += 8) {
        float a[4][4], b[4][2];
        #pragma unroll
        for (int mt = 0; mt < 4; ++mt) {
            const float* ap = As + (wr*64 + mt*16 + qr)*GAP + kb + qc;
            a[mt][0] = ap[0];
            a[mt][1] = ap[8*GAP];
            a[mt][2] = ap[4];
            a[mt][3] = ap[8*GAP + 4];
        }
        #pragma unroll
        for (int nt = 0; nt < 4; ++nt) {
            const float* bp = Bs + (kb + qc)*GBP + wc*32 + nt*8 + qr;
            b[nt][0] = bp[0];
            b[nt][1] = bp[4*GBP];
            #pragma unroll
            for (int mt = 0; mt < 4; ++mt)
                mma8(c[mt][nt], a[mt], b[nt]);
        }
    }
}

// =============================================================================
// Kernel 1: QKV projection (tf32 mma), scatter to (B,H,E,HD),
// fused per-CTA LN partial sums (deterministic, no atomics).
// =============================================================================
__global__ __launch_bounds__(256, 2) void gemm_qkv_kernel(
    const float* __restrict__ X,
    const float* __restrict__ Wq, const float* __restrict__ bq,
    const float* __restrict__ Wk, const float* __restrict__ bk,
    const float* __restrict__ Wv, const float* __restrict__ bv)
{
    extern __shared__ float dsm[];
    float* As0 = dsm;
    float* As1 = dsm + 128*GAP;
    float* Bs0 = dsm + 2*128*GAP;
    float* Bs1 = Bs0 + 32*GBP;

    const int t = blockIdx.z;
    const float* __restrict__ W    = (t==0) ? Wq : ((t==1) ? Wk : Wv);
    const float* __restrict__ bias = (t==0) ? bq : ((t==1) ? bk : bv);
    float* __restrict__ Y          = (t==0) ? g_q : ((t==1) ? g_k : g_v);

    const int bx = blockIdx.x, by = blockIdx.y;
    const int tid = threadIdx.x;
    const int w = tid >> 5, lane = tid & 31;
    const int wr = w >> 2, wc = w & 3;
    const int qr = lane >> 2, qc = lane & 3;

    float c[4][4][4];
    #pragma unroll
    for (int i = 0; i < 4; ++i)
        #pragma unroll
        for (int j = 0; j < 4; ++j)
            #pragma unroll
            for (int r = 0; r < 4; ++r) c[i][j][r] = 0.f;

    g_load(As0, Bs0, X, W, by, bx, 0, ND, NQKV, tid);
    CP_WAIT0();
    __syncthreads();

    int buf = 0;
    for (int kk = 32; kk < ND; kk += 32) {
        g_load(buf ? As0 : As1, buf ? Bs0 : Bs1, X, W, by, bx, kk, ND, NQKV, tid);
        g_compute(buf ? As1 : As0, buf ? Bs1 : Bs0, wr, wc, qr, qc, c);
        CP_WAIT0();
        __syncthreads();
        buf ^= 1;
    }
    g_compute(buf ? As1 : As0, buf ? Bs1 : Bs0, wr, wc, qr, qc, c);

    // epilogue: bias + scatter + LN partial sums
    float s = 0.f, s2 = 0.f;
    #pragma unroll
    for (int mt = 0; mt < 4; ++mt) {
        #pragma unroll
        for (int nt = 0; nt < 4; ++nt) {
            int gr = by*128 + wr*64 + mt*16 + qr;
            int gc = bx*128 + wc*32 + nt*8 + 2*qc;
            int h  = gc >> 6, hd = gc & 63;
            float bx0 = bias[gc], bx1 = bias[gc+1];
            float y0 = c[mt][nt][0] + bx0, y1 = c[mt][nt][1] + bx1;
            float y2 = c[mt][nt][2] + bx0, y3 = c[mt][nt][3] + bx1;
            s  += y0 + y1 + y2 + y3;
            s2 += y0*y0 + y1*y1 + y2*y2 + y3*y3;
            {
                int bi = gr >> 10, e = gr & 1023;
                float2 v = { y0, y1 };
                *(float2*)(Y + ((size_t)(bi*NH + h)*NE + e)*NHD + hd) = v;
            }
            {
                int gr2 = gr + 8;
                int bi = gr2 >> 10, e = gr2 & 1023;
                float2 v = { y2, y3 };
                *(float2*)(Y + ((size_t)(bi*NH + h)*NE + e)*NHD + hd) = v;
            }
        }
    }
    // warp reduce (all lanes of a warp share the same slab-half wc>>1)
    #pragma unroll
    for (int o = 16; o > 0; o >>= 1) {
        s  += __shfl_xor_sync(0xffffffffu, s,  o);
        s2 += __shfl_xor_sync(0xffffffffu, s2, o);
    }
    __shared__ float2 ws[8];
    if (lane == 0) ws[w] = make_float2(s, s2);
    __syncthreads();
    if (tid < 2) {
        const int half = tid;
        float2 a0 = ws[2*half], a1 = ws[2*half+1];
        float2 a2 = ws[2*half+4], a3 = ws[2*half+5];
        float2 r = { ((a0.x + a1.x) + (a2.x + a3.x)),
                     ((a0.y + a1.y) + (a2.y + a3.y)) };
        g_part[((t*64 + by)*4 + bx)*2 + half] = r;
    }
}

// =============================================================================
// Kernel 2: LN normalize pass (stats precomputed in g_part) + affine + ReLU,
// in place, output tf32-rounded.
// =============================================================================
__global__ __launch_bounds__(1024) void ln_kernel(
    const float* __restrict__ lw0, const float* __restrict__ lb0,
    const float* __restrict__ lw1, const float* __restrict__ lb1,
    const float* __restrict__ lw2, const float* __restrict__ lb2)
{
    const int t  = blockIdx.y;
    const int bh = blockIdx.x;
    float* __restrict__ Y        = (t==0) ? g_q : ((t==1) ? g_k : g_v);
    const float* __restrict__ lw = (t==0) ? lw0 : ((t==1) ? lw1 : lw2);
    const float* __restrict__ lb = (t==0) ? lb0 : ((t==1) ? lb1 : lb2);
    float* base = Y + (size_t)bh * SLAB;

    const int tid = threadIdx.x;
    __shared__ float bc[2];
    if (tid == 0) {
        const int b = bh >> 3, h = bh & 7;
        float s = 0.f, s2 = 0.f;
        #pragma unroll
        for (int i = 0; i < 8; ++i) {
            float2 p = g_part[((t*64 + (b*8 + i))*4 + (h >> 1))*2 + (h & 1)];
            s += p.x; s2 += p.y;
        }
        float mean = s * (1.f / SLAB);
        float var  = s2 * (1.f / SLAB) - mean*mean;
        bc[0] = mean;
        bc[1] = rsqrtf(var + LN_EPS);
    }
    __syncthreads();
    const float mean = bc[0], rstd = bc[1];

    for (int i = tid*4; i < SLAB; i += 1024*4) {
        float4 v = *(const float4*)(base + i);
        float4 g = *(const float4*)(lw + i);
        float4 b = *(const float4*)(lb + i);
        v.x = tf32r(fmaxf(0.f, (v.x - mean)*rstd*g.x + b.x));
        v.y = tf32r(fmaxf(0.f, (v.y - mean)*rstd*g.y + b.y));
        v.z = tf32r(fmaxf(0.f, (v.z - mean)*rstd*g.z + b.z));
        v.w = tf32r(fmaxf(0.f, (v.w - mean)*rstd*g.w + b.w));
        *(float4*)(base + i) = v;
    }
}

// =============================================================================
// Kernel 3: flash attention (tf32 mma). grid=(8,64), 256 thr = 8 warps.
// BQ=128, BKV=64 -> smem 106.5 KB -> 2 CTAs/SM (softmax of one CTA overlaps
// mma of the other). Q fragments in registers; K/V 2-stage cp.async.
//   Kb[2]: [64][68], Vb[2]: [64][72], Ss: [128][68]
// =============================================================================
#define BKV 64
#define KP 68
#define VP 72
#define SP 68
#define ATTN_SMEM ((2*BKV*KP + 2*BKV*VP + 128*SP)*4)   // 106496 B

__device__ __forceinline__ void attn_load_kv(
    float* Kb, float* Vb, const float* __restrict__ kgt,
    const float* __restrict__ vgt, int tid)
{
    #pragma unroll
    for (int l = 0; l < 4; ++l) {
        int idx = l*256 + tid;
        int row = idx >> 4, c4 = (idx & 15) << 2;   // row 0..63
        cp_async16(Kb + row*KP + c4, kgt + row*NHD + c4);
        cp_async16(Vb + row*VP + c4, vgt + row*NHD + c4);
    }
    CP_COMMIT();
}

__global__ __launch_bounds__(256, 2) void attn_kernel()
{
    extern __shared__ float sm[];
    float* Kb0 = sm;
    float* Kb1 = Kb0 + BKV*KP;
    float* Vb0 = Kb1 + BKV*KP;
    float* Vb1 = Vb0 + BKV*VP;
    float* Ss  = Vb1 + BKV*VP;

    const int bh = blockIdx.y;
    const int qb = blockIdx.x;
    const int tid = threadIdx.x;
    const int w = tid >> 5, lane = tid & 31;
    const int qr = lane >> 2, qc = lane & 3;
    const int r0 = w*16 + qr;

    const float* __restrict__ qg = g_q + (size_t)bh*SLAB + (size_t)qb*128*NHD;
    const float* __restrict__ kg = g_k + (size_t)bh*SLAB;
    const float* __restrict__ vg = g_v + (size_t)bh*SLAB;

    attn_load_kv(Kb0, Vb0, kg, vg, tid);

    // stage Q tile into Ss, lift fragments into registers
    #pragma unroll
    for (int l = 0; l < 8; ++l) {
        int idx = l*256 + tid;
        int row = idx >> 4, c4 = (idx & 15) << 2;
        *(float4*)(Ss + row*SP + c4) = *(const float4*)(qg + row*NHD + c4);
    }
    __syncthreads();
    float qf[8][4];
    #pragma unroll
    for (int kbi = 0; kbi < 8; ++kbi) {
        const float* ap = Ss + r0*SP + kbi*8 + qc;
        qf[kbi][0] = ap[0];
        qf[kbi][1] = ap[8*SP];
        qf[kbi][2] = ap[4];
        qf[kbi][3] = ap[8*SP + 4];
    }

    float o[8][4];
    #pragma unroll
    for (int nt = 0; nt < 8; ++nt)
        #pragma unroll
        for (int r = 0; r < 4; ++r) o[nt][r] = 0.f;
    float m0 = -INFINITY, m1 = -INFINITY, l0 = 0.f, l1 = 0.f;

    for (int kt = 0; kt < NE/BKV; ++kt) {
        const int buf = kt & 1;
        float* Kc = buf ? Kb1 : Kb0;
        float* Vc = buf ? Vb1 : Vb0;

        CP_WAIT0();
        __syncthreads();   // publish tile kt; retires PV reads of kt-1

        if (kt + 1 < NE/BKV) {
            attn_load_kv(buf ? Kb0 : Kb1, buf ? Vb0 : Vb1,
                         kg + (size_t)(kt+1)*BKV*NHD,
                         vg + (size_t)(kt+1)*BKV*NHD, tid);
        }

        // ---- S = Q @ K^T  (128 q rows x 64 key cols)
        float s[8][4];
        #pragma unroll
        for (int nt = 0; nt < 8; ++nt)
            #pragma unroll
            for (int r = 0; r < 4; ++r) s[nt][r] = 0.f;

        #pragma unroll
        for (int kbi = 0; kbi < 8; ++kbi) {
            #pragma unroll
            for (int nt = 0; nt < 8; ++nt) {
                const float* bp = Kc + (nt*8 + qr)*KP + kbi*8 + qc;
                float b[2] = { bp[0], bp[4] };
                mma8(s[nt], qf[kbi], b);
            }
        }

        // ---- online softmax (rows r0 and r0+8; quad lanes share a row)
        float mx0 = s[0][0], mx1 = s[0][2];
        #pragma unroll
        for (int nt = 0; nt < 8; ++nt) {
            mx0 = fmaxf(mx0, fmaxf(s[nt][0], s[nt][1]));
            mx1 = fmaxf(mx1, fmaxf(s[nt][2], s[nt][3]));
        }
        mx0 = fmaxf(mx0, __shfl_xor_sync(0xffffffffu, mx0, 1));
        mx0 = fmaxf(mx0, __shfl_xor_sync(0xffffffffu, mx0, 2));
        mx1 = fmaxf(mx1, __shfl_xor_sync(0xffffffffu, mx1, 1));
        mx1 = fmaxf(mx1, __shfl_xor_sync(0xffffffffu, mx1, 2));
        float mn0 = fmaxf(m0, mx0), mn1 = fmaxf(m1, mx1);
        float al0 = exp2a((m0 - mn0)*SC2);
        float al1 = exp2a((m1 - mn1)*SC2);
        m0 = mn0; m1 = mn1;
        l0 *= al0; l1 *= al1;
        #pragma unroll
        for (int nt = 0; nt < 8; ++nt) {
            o[nt][0] *= al0; o[nt][1] *= al0;
            o[nt][2] *= al1; o[nt][3] *= al1;
        }
        const float base0 = mn0*SC2, base1 = mn1*SC2;
        #pragma unroll
        for (int nt = 0; nt < 8; ++nt) {
            float p0 = exp2a(fmaf(s[nt][0], SC2, -base0));
            float p1 = exp2a(fmaf(s[nt][1], SC2, -base0));
            float p2 = exp2a(fmaf(s[nt][2], SC2, -base1));
            float p3 = exp2a(fmaf(s[nt][3], SC2, -base1));
            l0 += p0 + p1;
            l1 += p2 + p3;
            int col = nt*8 + 2*qc;
            float2 v0 = { tf32r(p0), tf32r(p1) };
            float2 v1 = { tf32r(p2), tf32r(p3) };
            *(float2*)(Ss + r0*SP + col)       = v0;
            *(float2*)(Ss + (r0 + 8)*SP + col) = v1;
        }
        __syncthreads();

        // ---- O += P @ V  (64 kv rows)
        #pragma unroll
        for (int kb = 0; kb < BKV; kb += 8) {
            float a[4];
            const float* ap = Ss + r0*SP + kb + qc;
            a[0] = ap[0]; a[1] = ap[8*SP]; a[2] = ap[4]; a[3] = ap[8*SP + 4];
            #pragma unroll
            for (int nt = 0; nt < 8; ++nt) {
                const float* bp = Vc + (kb + qc)*VP + nt*8 + qr;
                float b[2] = { bp[0], bp[4*VP] };
                mma8(o[nt], a, b);
            }
        }
    }

    l0 += __shfl_xor_sync(0xffffffffu, l0, 1);
    l0 += __shfl_xor_sync(0xffffffffu, l0, 2);
    l1 += __shfl_xor_sync(0xffffffffu, l1, 1);
    l1 += __shfl_xor_sync(0xffffffffu, l1, 2);
    const float inv0 = 1.f / l0, inv1 = 1.f / l1;

    const int bi = bh >> 3;
    const int h  = bh & 7;
    #pragma unroll
    for (int nt = 0; nt < 8; ++nt) {
        int hd = nt*8 + 2*qc;
        {
            int e = qb*128 + r0;
            float2 v = { tf32r(o[nt][0]*inv0), tf32r(o[nt][1]*inv0) };
            *(float2*)(g_ctx + ((size_t)(bi*NE + e)*NH + h)*NHD + hd) = v;
        }
        {
            int e = qb*128 + r0 + 8;
            float2 v = { tf32r(o[nt][2]*inv1), tf32r(o[nt][3]*inv1) };
            *(float2*)(g_ctx + ((size_t)(bi*NE + e)*NH + h)*NHD + hd) = v;
        }
    }
}

// =============================================================================
// Kernel 4: output projection (tf32 mma) out = relu(ctx @ Wo + bo)
// =============================================================================
__global__ __launch_bounds__(256, 2) void gemm_out_kernel(
    const float* __restrict__ Wo, const float* __restrict__ bo,
    float* __restrict__ out)
{
    extern __shared__ float dsm[];
    float* As0 = dsm;
    float* As1 = dsm + 128*GAP;
    float* Bs0 = dsm + 2*128*GAP;
    float* Bs1 = Bs0 + 32*GBP;

    const int bx = blockIdx.x, by = blockIdx.y;
    const int tid = threadIdx.x;
    const int w = tid >> 5, lane = tid & 31;
    const int wr = w >> 2, wc = w & 3;
    const int qr = lane >> 2, qc = lane & 3;

    float c[4][4][4];
    #pragma unroll
    for (int i = 0; i < 4; ++i)
        #pragma unroll
        for (int j = 0; j < 4; ++j)
            #pragma unroll
            for (int r = 0; r < 4; ++r) c[i][j][r] = 0.f;

    g_load(As0, Bs0, g_ctx, Wo, by, bx, 0, NQKV, ND, tid);
    CP_WAIT0();
    __syncthreads();

    int buf = 0;
    for (int kk = 32; kk < NQKV; kk += 32) {
        g_load(buf ? As0 : As1, buf ? Bs0 : Bs1, g_ctx, Wo, by, bx, kk, NQKV, ND, tid);
        g_compute(buf ? As1 : As0, buf ? Bs1 : Bs0, wr, wc, qr, qc, c);
        CP_WAIT0();
        __syncthreads();
        buf ^= 1;
    }
    g_compute(buf ? As1 : As0, buf ? Bs1 : Bs0, wr, wc, qr, qc, c);

    #pragma unroll
    for (int mt = 0; mt < 4; ++mt) {
        #pragma unroll
        for (int nt = 0; nt < 4; ++nt) {
            int gr = by*128 + wr*64 + mt*16 + qr;
            int gc = bx*128 + wc*32 + nt*8 + 2*qc;
            float bx0 = bo[gc], bx1 = bo[gc+1];
            float2 v0 = { fmaxf(0.f, c[mt][nt][0] + bx0),
                          fmaxf(0.f, c[mt][nt][1] + bx1) };
            float2 v1 = { fmaxf(0.f, c[mt][nt][2] + bx0),
                          fmaxf(0.f, c[mt][nt][3] + bx1) };
            *(float2*)(out + (size_t)gr*ND + gc)     = v0;
            *(float2*)(out + (size_t)(gr+8)*ND + gc) = v1;
        }
    }
}

// =============================================================================
extern "C" void kernel_launch(void* const* d_in, const int* in_sizes, int n_in,
                              void* d_out, int out_size)
{
    const float* features = (const float*)d_in[0];
    const float* Wq   = (const float*)d_in[1];
    const float* bq   = (const float*)d_in[2];
    const float* lnqw = (const float*)d_in[3];
    const float* lnqb = (const float*)d_in[4];
    const float* Wk   = (const float*)d_in[5];
    const float* bk   = (const float*)d_in[6];
    const float* lnkw = (const float*)d_in[7];
    const float* lnkb = (const float*)d_in[8];
    const float* Wv   = (const float*)d_in[9];
    const float* bv   = (const float*)d_in[10];
    const float* lnvw = (const float*)d_in[11];
    const float* lnvb = (const float*)d_in[12];
    const float* Wo   = (const float*)d_in[13];
    const float* bo   = (const float*)d_in[14];
    float* out = (float*)d_out;

    cudaFuncSetAttribute(attn_kernel,
                         cudaFuncAttributeMaxDynamicSharedMemorySize, ATTN_SMEM);
    cudaFuncSetAttribute(gemm_qkv_kernel,
                         cudaFuncAttributeMaxDynamicSharedMemorySize, GEMM_SMEM);
    cudaFuncSetAttribute(gemm_out_kernel,
                         cudaFuncAttributeMaxDynamicSharedMemorySize, GEMM_SMEM);

    gemm_qkv_kernel<<<dim3(NQKV/128, M_ROWS/128, 3), 256, GEMM_SMEM>>>(
        features, Wq, bq, Wk, bk, Wv, bv);
    ln_kernel<<<dim3(NBH, 3), 1024>>>(lnqw, lnqb, lnkw, lnkb, lnvw, lnvb);
    attn_kernel<<<dim3(NE/128, NBH), 256, ATTN_SMEM>>>();
    gemm_out_kernel<<<dim3(ND/128, M_ROWS/128), 256, GEMM_SMEM>>>(Wo, bo, out);
}

// round 8
// speedup vs baseline: 1.1227x; 1.0113x over previous
#include <cuda_runtime.h>
#include <math.h>
#include <stdint.h>

#define NB 8
#define NE 1024
#define ND 512
#define NQKV 512
#define NH 8
#define NHD 64
#define NBH (NB*NH)         // 64
#define M_ROWS (NB*NE)      // 8192
#define SLAB (NE*NHD)       // 65536
#define LN_EPS 1e-5f
#define ATTN_SCALE 0.044194173824159216f           // 1/sqrt(512)
#define SC2 (ATTN_SCALE * 1.4426950408889634f)     // scale * log2(e)

// ---------------- scratch (device globals; no runtime allocation) -------------
__device__ float g_q[NBH*SLAB];        // (B,H,E,HD), tf32-rounded after LN
__device__ float g_k[NBH*SLAB];
__device__ float g_v[NBH*SLAB];
__device__ float g_ctx[M_ROWS*NQKV];   // (B,E,H,HD), tf32-rounded
// per-CTA LN partial sums: [t][by][bx][half] -> (sum, sumsq); deterministic
__device__ float2 g_part[3*64*4*2];

// ---------------- helpers ------------------------------------------------------
__device__ __forceinline__ float tf32r(float x) {
    uint32_t u;
    asm("cvt.rna.tf32.f32 %0, %1;" : "=r"(u) : "f"(x));
    return __uint_as_float(u);
}
__device__ __forceinline__ float exp2a(float x) {
    float y;
    asm("ex2.approx.ftz.f32 %0, %1;" : "=f"(y) : "f"(x));
    return y;
}
__device__ __forceinline__ void mma8(float c[4], const float a[4], const float b[2]) {
    asm volatile(
        "mma.sync.aligned.m16n8k8.row.col.f32.tf32.tf32.f32 "
        "{%0,%1,%2,%3}, {%4,%5,%6,%7}, {%8,%9}, {%0,%1,%2,%3};\n"
        : "+f"(c[0]), "+f"(c[1]), "+f"(c[2]), "+f"(c[3])
        : "r"(__float_as_uint(a[0])), "r"(__float_as_uint(a[1])),
          "r"(__float_as_uint(a[2])), "r"(__float_as_uint(a[3])),
          "r"(__float_as_uint(b[0])), "r"(__float_as_uint(b[1])));
}
__device__ __forceinline__ void cp_async16(void* smem, const void* gmem) {
    uint32_t s = (uint32_t)__cvta_generic_to_shared(smem);
    asm volatile("cp.async.cg.shared.global [%0], [%1], 16;\n" :: "r"(s), "l"(gmem));
}
#define CP_COMMIT() asm volatile("cp.async.commit_group;\n" ::: "memory")
#define CP_WAIT0()  asm volatile("cp.async.wait_group 0;\n" ::: "memory")

// =============================================================================
// tf32 GEMM core: 128x128 block, k-step 32, 2-stage cp.async (round-5 proven),
// 256 threads = 8 warps (2x4), warp tile 64x32, m16n8k8 mma.
//   As: m-major [128][36], Bs: k-major [32][136]  (frag-conflict-free)
// =============================================================================
#define GAP 36
#define GBP 136
#define GEMM_SMEM ((2*128*GAP + 2*32*GBP)*4)

__device__ __forceinline__ void g_load(
    float* As, float* Bs,
    const float* __restrict__ A, const float* __restrict__ B,
    int by, int bx, int kk, int lda, int ldb, int tid)
{
    #pragma unroll
    for (int l = 0; l < 4; ++l) {
        int idx = l*256 + tid;
        int row = idx >> 3, k4 = (idx & 7) << 2;
        cp_async16(As + row*GAP + k4, A + (size_t)(by*128 + row)*lda + kk + k4);
    }
    #pragma unroll
    for (int l = 0; l < 4; ++l) {
        int idx = l*256 + tid;
        int kr = idx >> 5, n4 = (idx & 31) << 2;
        cp_async16(Bs + kr*GBP + n4, B + (size_t)(kk + kr)*ldb + bx*128 + n4);
    }
    CP_COMMIT();
}

__device__ __forceinline__ void g_compute(
    const float* As, const float* Bs,
    int wr, int wc, int qr, int qc, float c[4][4][4])
{
    #pragma unroll
    for (int kb = 0; kb < 32; kb += 8) {
        float a[4][4], b[4][2];
        #pragma unroll
        for (int mt = 0; mt < 4; ++mt) {
            const float* ap = As + (wr*64 + mt*16 + qr)*GAP + kb + qc;
            a[mt][0] = ap[0];
            a[mt][1] = ap[8*GAP];
            a[mt][2] = ap[4];
            a[mt][3] = ap[8*GAP + 4];
        }
        #pragma unroll
        for (int nt = 0; nt < 4; ++nt) {
            const float* bp = Bs + (kb + qc)*GBP + wc*32 + nt*8 + qr;
            b[nt][0] = bp[0];
            b[nt][1] = bp[4*GBP];
            #pragma unroll
            for (int mt = 0; mt < 4; ++mt)
                mma8(c[mt][nt], a[mt], b[nt]);
        }
    }
}

// =============================================================================
// Kernel 1: QKV projection (tf32 mma), scatter to (B,H,E,HD),
// fused per-CTA LN partial sums (deterministic, no atomics).
// =============================================================================
__global__ __launch_bounds__(256, 2) void gemm_qkv_kernel(
    const float* __restrict__ X,
    const float* __restrict__ Wq, const float* __restrict__ bq,
    const float* __restrict__ Wk, const float* __restrict__ bk,
    const float* __restrict__ Wv, const float* __restrict__ bv)
{
    extern __shared__ float dsm[];
    float* As0 = dsm;
    float* As1 = dsm + 128*GAP;
    float* Bs0 = dsm + 2*128*GAP;
    float* Bs1 = Bs0 + 32*GBP;

    const int t = blockIdx.z;
    const float* __restrict__ W    = (t==0) ? Wq : ((t==1) ? Wk : Wv);
    const float* __restrict__ bias = (t==0) ? bq : ((t==1) ? bk : bv);
    float* __restrict__ Y          = (t==0) ? g_q : ((t==1) ? g_k : g_v);

    const int bx = blockIdx.x, by = blockIdx.y;
    const int tid = threadIdx.x;
    const int w = tid >> 5, lane = tid & 31;
    const int wr = w >> 2, wc = w & 3;
    const int qr = lane >> 2, qc = lane & 3;

    float c[4][4][4];
    #pragma unroll
    for (int i = 0; i < 4; ++i)
        #pragma unroll
        for (int j = 0; j < 4; ++j)
            #pragma unroll
            for (int r = 0; r < 4; ++r) c[i][j][r] = 0.f;

    g_load(As0, Bs0, X, W, by, bx, 0, ND, NQKV, tid);
    CP_WAIT0();
    __syncthreads();

    int buf = 0;
    for (int kk = 32; kk < ND; kk += 32) {
        g_load(buf ? As0 : As1, buf ? Bs0 : Bs1, X, W, by, bx, kk, ND, NQKV, tid);
        g_compute(buf ? As1 : As0, buf ? Bs1 : Bs0, wr, wc, qr, qc, c);
        CP_WAIT0();
        __syncthreads();
        buf ^= 1;
    }
    g_compute(buf ? As1 : As0, buf ? Bs1 : Bs0, wr, wc, qr, qc, c);

    // epilogue: bias + scatter + LN partial sums
    float s = 0.f, s2 = 0.f;
    #pragma unroll
    for (int mt = 0; mt < 4; ++mt) {
        #pragma unroll
        for (int nt = 0; nt < 4; ++nt) {
            int gr = by*128 + wr*64 + mt*16 + qr;
            int gc = bx*128 + wc*32 + nt*8 + 2*qc;
            int h  = gc >> 6, hd = gc & 63;
            float bx0 = bias[gc], bx1 = bias[gc+1];
            float y0 = c[mt][nt][0] + bx0, y1 = c[mt][nt][1] + bx1;
            float y2 = c[mt][nt][2] + bx0, y3 = c[mt][nt][3] + bx1;
            s  += y0 + y1 + y2 + y3;
            s2 += y0*y0 + y1*y1 + y2*y2 + y3*y3;
            {
                int bi = gr >> 10, e = gr & 1023;
                float2 v = { y0, y1 };
                *(float2*)(Y + ((size_t)(bi*NH + h)*NE + e)*NHD + hd) = v;
            }
            {
                int gr2 = gr + 8;
                int bi = gr2 >> 10, e = gr2 & 1023;
                float2 v = { y2, y3 };
                *(float2*)(Y + ((size_t)(bi*NH + h)*NE + e)*NHD + hd) = v;
            }
        }
    }
    // warp reduce (all lanes of a warp share the same slab-half wc>>1)
    #pragma unroll
    for (int o = 16; o > 0; o >>= 1) {
        s  += __shfl_xor_sync(0xffffffffu, s,  o);
        s2 += __shfl_xor_sync(0xffffffffu, s2, o);
    }
    __shared__ float2 ws[8];
    if (lane == 0) ws[w] = make_float2(s, s2);
    __syncthreads();
    if (tid < 2) {
        const int half = tid;
        float2 a0 = ws[2*half], a1 = ws[2*half+1];
        float2 a2 = ws[2*half+4], a3 = ws[2*half+5];
        float2 r = { ((a0.x + a1.x) + (a2.x + a3.x)),
                     ((a0.y + a1.y) + (a2.y + a3.y)) };
        g_part[((t*64 + by)*4 + bx)*2 + half] = r;
    }
}

// =============================================================================
// Kernel 2: LN normalize pass (stats precomputed in g_part) + affine + ReLU,
// in place, output tf32-rounded.
// =============================================================================
__global__ __launch_bounds__(1024) void ln_kernel(
    const float* __restrict__ lw0, const float* __restrict__ lb0,
    const float* __restrict__ lw1, const float* __restrict__ lb1,
    const float* __restrict__ lw2, const float* __restrict__ lb2)
{
    const int t  = blockIdx.y;
    const int bh = blockIdx.x;
    float* __restrict__ Y        = (t==0) ? g_q : ((t==1) ? g_k : g_v);
    const float* __restrict__ lw = (t==0) ? lw0 : ((t==1) ? lw1 : lw2);
    const float* __restrict__ lb = (t==0) ? lb0 : ((t==1) ? lb1 : lb2);
    float* base = Y + (size_t)bh * SLAB;

    const int tid = threadIdx.x;
    __shared__ float bc[2];
    if (tid == 0) {
        const int b = bh >> 3, h = bh & 7;
        float s = 0.f, s2 = 0.f;
        #pragma unroll
        for (int i = 0; i < 8; ++i) {
            float2 p = g_part[((t*64 + (b*8 + i))*4 + (h >> 1))*2 + (h & 1)];
            s += p.x; s2 += p.y;
        }
        float mean = s * (1.f / SLAB);
        float var  = s2 * (1.f / SLAB) - mean*mean;
        bc[0] = mean;
        bc[1] = rsqrtf(var + LN_EPS);
    }
    __syncthreads();
    const float mean = bc[0], rstd = bc[1];

    for (int i = tid*4; i < SLAB; i += 1024*4) {
        float4 v = *(const float4*)(base + i);
        float4 g = *(const float4*)(lw + i);
        float4 b = *(const float4*)(lb + i);
        v.x = tf32r(fmaxf(0.f, (v.x - mean)*rstd*g.x + b.x));
        v.y = tf32r(fmaxf(0.f, (v.y - mean)*rstd*g.y + b.y));
        v.z = tf32r(fmaxf(0.f, (v.z - mean)*rstd*g.z + b.z));
        v.w = tf32r(fmaxf(0.f, (v.w - mean)*rstd*g.w + b.w));
        *(float4*)(base + i) = v;
    }
}

// =============================================================================
// Kernel 3: flash attention (tf32 mma). grid=(8,64), 256 thr = 8 warps.
// BQ=128, BKV=64. NO register cap (avoid spills); occupancy falls where it may.
// Q fragments in registers; K/V 2-stage cp.async.
//   Kb[2]: [64][68], Vb[2]: [64][72], Ss: [128][68]
// =============================================================================
#define BKV 64
#define KP 68
#define VP 72
#define SP 68
#define ATTN_SMEM ((2*BKV*KP + 2*BKV*VP + 128*SP)*4)   // 106496 B

__device__ __forceinline__ void attn_load_kv(
    float* Kb, float* Vb, const float* __restrict__ kgt,
    const float* __restrict__ vgt, int tid)
{
    #pragma unroll
    for (int l = 0; l < 4; ++l) {
        int idx = l*256 + tid;
        int row = idx >> 4, c4 = (idx & 15) << 2;   // row 0..63
        cp_async16(Kb + row*KP + c4, kgt + row*NHD + c4);
        cp_async16(Vb + row*VP + c4, vgt + row*NHD + c4);
    }
    CP_COMMIT();
}

__global__ __launch_bounds__(256) void attn_kernel()
{
    extern __shared__ float sm[];
    float* Kb0 = sm;
    float* Kb1 = Kb0 + BKV*KP;
    float* Vb0 = Kb1 + BKV*KP;
    float* Vb1 = Vb0 + BKV*VP;
    float* Ss  = Vb1 + BKV*VP;

    const int bh = blockIdx.y;
    const int qb = blockIdx.x;
    const int tid = threadIdx.x;
    const int w = tid >> 5, lane = tid & 31;
    const int qr = lane >> 2, qc = lane & 3;
    const int r0 = w*16 + qr;

    const float* __restrict__ qg = g_q + (size_t)bh*SLAB + (size_t)qb*128*NHD;
    const float* __restrict__ kg = g_k + (size_t)bh*SLAB;
    const float* __restrict__ vg = g_v + (size_t)bh*SLAB;

    attn_load_kv(Kb0, Vb0, kg, vg, tid);

    // stage Q tile into Ss, lift fragments into registers
    #pragma unroll
    for (int l = 0; l < 8; ++l) {
        int idx = l*256 + tid;
        int row = idx >> 4, c4 = (idx & 15) << 2;
        *(float4*)(Ss + row*SP + c4) = *(const float4*)(qg + row*NHD + c4);
    }
    __syncthreads();
    float qf[8][4];
    #pragma unroll
    for (int kbi = 0; kbi < 8; ++kbi) {
        const float* ap = Ss + r0*SP + kbi*8 + qc;
        qf[kbi][0] = ap[0];
        qf[kbi][1] = ap[8*SP];
        qf[kbi][2] = ap[4];
        qf[kbi][3] = ap[8*SP + 4];
    }

    float o[8][4];
    #pragma unroll
    for (int nt = 0; nt < 8; ++nt)
        #pragma unroll
        for (int r = 0; r < 4; ++r) o[nt][r] = 0.f;
    float m0 = -INFINITY, m1 = -INFINITY, l0 = 0.f, l1 = 0.f;

    for (int kt = 0; kt < NE/BKV; ++kt) {
        const int buf = kt & 1;
        float* Kc = buf ? Kb1 : Kb0;
        float* Vc = buf ? Vb1 : Vb0;

        CP_WAIT0();
        __syncthreads();   // publish tile kt; retires PV reads of kt-1

        if (kt + 1 < NE/BKV) {
            attn_load_kv(buf ? Kb0 : Kb1, buf ? Vb0 : Vb1,
                         kg + (size_t)(kt+1)*BKV*NHD,
                         vg + (size_t)(kt+1)*BKV*NHD, tid);
        }

        // ---- S = Q @ K^T  (128 q rows x 64 key cols)
        float s[8][4];
        #pragma unroll
        for (int nt = 0; nt < 8; ++nt)
            #pragma unroll
            for (int r = 0; r < 4; ++r) s[nt][r] = 0.f;

        #pragma unroll
        for (int kbi = 0; kbi < 8; ++kbi) {
            #pragma unroll
            for (int nt = 0; nt < 8; ++nt) {
                const float* bp = Kc + (nt*8 + qr)*KP + kbi*8 + qc;
                float b[2] = { bp[0], bp[4] };
                mma8(s[nt], qf[kbi], b);
            }
        }

        // ---- online softmax (rows r0 and r0+8; quad lanes share a row)
        float mx0 = s[0][0], mx1 = s[0][2];
        #pragma unroll
        for (int nt = 0; nt < 8; ++nt) {
            mx0 = fmaxf(mx0, fmaxf(s[nt][0], s[nt][1]));
            mx1 = fmaxf(mx1, fmaxf(s[nt][2], s[nt][3]));
        }
        mx0 = fmaxf(mx0, __shfl_xor_sync(0xffffffffu, mx0, 1));
        mx0 = fmaxf(mx0, __shfl_xor_sync(0xffffffffu, mx0, 2));
        mx1 = fmaxf(mx1, __shfl_xor_sync(0xffffffffu, mx1, 1));
        mx1 = fmaxf(mx1, __shfl_xor_sync(0xffffffffu, mx1, 2));
        float mn0 = fmaxf(m0, mx0), mn1 = fmaxf(m1, mx1);
        float al0 = exp2a((m0 - mn0)*SC2);
        float al1 = exp2a((m1 - mn1)*SC2);
        m0 = mn0; m1 = mn1;
        l0 *= al0; l1 *= al1;
        #pragma unroll
        for (int nt = 0; nt < 8; ++nt) {
            o[nt][0] *= al0; o[nt][1] *= al0;
            o[nt][2] *= al1; o[nt][3] *= al1;
        }
        const float base0 = mn0*SC2, base1 = mn1*SC2;
        #pragma unroll
        for (int nt = 0; nt < 8; ++nt) {
            float p0 = exp2a(fmaf(s[nt][0], SC2, -base0));
            float p1 = exp2a(fmaf(s[nt][1], SC2, -base0));
            float p2 = exp2a(fmaf(s[nt][2], SC2, -base1));
            float p3 = exp2a(fmaf(s[nt][3], SC2, -base1));
            l0 += p0 + p1;
            l1 += p2 + p3;
            int col = nt*8 + 2*qc;
            float2 v0 = { p0, p1 };     // fp32; mma truncates to tf32 itself
            float2 v1 = { p2, p3 };
            *(float2*)(Ss + r0*SP + col)       = v0;
            *(float2*)(Ss + (r0 + 8)*SP + col) = v1;
        }
        __syncthreads();

        // ---- O += P @ V  (64 kv rows)
        #pragma unroll
        for (int kb = 0; kb < BKV; kb += 8) {
            float a[4];
            const float* ap = Ss + r0*SP + kb + qc;
            a[0] = ap[0]; a[1] = ap[8*SP]; a[2] = ap[4]; a[3] = ap[8*SP + 4];
            #pragma unroll
            for (int nt = 0; nt < 8; ++nt) {
                const float* bp = Vc + (kb + qc)*VP + nt*8 + qr;
                float b[2] = { bp[0], bp[4*VP] };
                mma8(o[nt], a, b);
            }
        }
    }

    l0 += __shfl_xor_sync(0xffffffffu, l0, 1);
    l0 += __shfl_xor_sync(0xffffffffu, l0, 2);
    l1 += __shfl_xor_sync(0xffffffffu, l1, 1);
    l1 += __shfl_xor_sync(0xffffffffu, l1, 2);
    const float inv0 = 1.f / l0, inv1 = 1.f / l1;

    const int bi = bh >> 3;
    const int h  = bh & 7;
    #pragma unroll
    for (int nt = 0; nt < 8; ++nt) {
        int hd = nt*8 + 2*qc;
        {
            int e = qb*128 + r0;
            float2 v = { tf32r(o[nt][0]*inv0), tf32r(o[nt][1]*inv0) };
            *(float2*)(g_ctx + ((size_t)(bi*NE + e)*NH + h)*NHD + hd) = v;
        }
        {
            int e = qb*128 + r0 + 8;
            float2 v = { tf32r(o[nt][2]*inv1), tf32r(o[nt][3]*inv1) };
            *(float2*)(g_ctx + ((size_t)(bi*NE + e)*NH + h)*NHD + hd) = v;
        }
    }
}

// =============================================================================
// Kernel 4: output projection (tf32 mma) out = relu(ctx @ Wo + bo)
// =============================================================================
__global__ __launch_bounds__(256, 2) void gemm_out_kernel(
    const float* __restrict__ Wo, const float* __restrict__ bo,
    float* __restrict__ out)
{
    extern __shared__ float dsm[];
    float* As0 = dsm;
    float* As1 = dsm + 128*GAP;
    float* Bs0 = dsm + 2*128*GAP;
    float* Bs1 = Bs0 + 32*GBP;

    const int bx = blockIdx.x, by = blockIdx.y;
    const int tid = threadIdx.x;
    const int w = tid >> 5, lane = tid & 31;
    const int wr = w >> 2, wc = w & 3;
    const int qr = lane >> 2, qc = lane & 3;

    float c[4][4][4];
    #pragma unroll
    for (int i = 0; i < 4; ++i)
        #pragma unroll
        for (int j = 0; j < 4; ++j)
            #pragma unroll
            for (int r = 0; r < 4; ++r) c[i][j][r] = 0.f;

    g_load(As0, Bs0, g_ctx, Wo, by, bx, 0, NQKV, ND, tid);
    CP_WAIT0();
    __syncthreads();

    int buf = 0;
    for (int kk = 32; kk < NQKV; kk += 32) {
        g_load(buf ? As0 : As1, buf ? Bs0 : Bs1, g_ctx, Wo, by, bx, kk, NQKV, ND, tid);
        g_compute(buf ? As1 : As0, buf ? Bs1 : Bs0, wr, wc, qr, qc, c);
        CP_WAIT0();
        __syncthreads();
        buf ^= 1;
    }
    g_compute(buf ? As1 : As0, buf ? Bs1 : Bs0, wr, wc, qr, qc, c);

    #pragma unroll
    for (int mt = 0; mt < 4; ++mt) {
        #pragma unroll
        for (int nt = 0; nt < 4; ++nt) {
            int gr = by*128 + wr*64 + mt*16 + qr;
            int gc = bx*128 + wc*32 + nt*8 + 2*qc;
            float bx0 = bo[gc], bx1 = bo[gc+1];
            float2 v0 = { fmaxf(0.f, c[mt][nt][0] + bx0),
                          fmaxf(0.f, c[mt][nt][1] + bx1) };
            float2 v1 = { fmaxf(0.f, c[mt][nt][2] + bx0),
                          fmaxf(0.f, c[mt][nt][3] + bx1) };
            *(float2*)(out + (size_t)gr*ND + gc)     = v0;
            *(float2*)(out + (size_t)(gr+8)*ND + gc) = v1;
        }
    }
}

// =============================================================================
extern "C" void kernel_launch(void* const* d_in, const int* in_sizes, int n_in,
                              void* d_out, int out_size)
{
    const float* features = (const float*)d_in[0];
    const float* Wq   = (const float*)d_in[1];
    const float* bq   = (const float*)d_in[2];
    const float* lnqw = (const float*)d_in[3];
    const float* lnqb = (const float*)d_in[4];
    const float* Wk   = (const float*)d_in[5];
    const float* bk   = (const float*)d_in[6];
    const float* lnkw = (const float*)d_in[7];
    const float* lnkb = (const float*)d_in[8];
    const float* Wv   = (const float*)d_in[9];
    const float* bv   = (const float*)d_in[10];
    const float* lnvw = (const float*)d_in[11];
    const float* lnvb = (const float*)d_in[12];
    const float* Wo   = (const float*)d_in[13];
    const float* bo   = (const float*)d_in[14];
    float* out = (float*)d_out;

    cudaFuncSetAttribute(attn_kernel,
                         cudaFuncAttributeMaxDynamicSharedMemorySize, ATTN_SMEM);
    cudaFuncSetAttribute(gemm_qkv_kernel,
                         cudaFuncAttributeMaxDynamicSharedMemorySize, GEMM_SMEM);
    cudaFuncSetAttribute(gemm_out_kernel,
                         cudaFuncAttributeMaxDynamicSharedMemorySize, GEMM_SMEM);

    gemm_qkv_kernel<<<dim3(NQKV/128, M_ROWS/128, 3), 256, GEMM_SMEM>>>(
        features, Wq, bq, Wk, bk, Wv, bv);
    ln_kernel<<<dim3(NBH, 3), 1024>>>(lnqw, lnqb, lnkw, lnkb, lnvw, lnvb);
    attn_kernel<<<dim3(NE/128, NBH), 256, ATTN_SMEM>>>();
    gemm_out_kernel<<<dim3(ND/128, M_ROWS/128), 256, GEMM_SMEM>>>(Wo, bo, out);
}